// round 1
// baseline (speedup 1.0000x reference)
#include <cuda_runtime.h>
#include <cuda_bf16.h>

// DefocusBlur: depthwise 17x17 cross-correlation, reflect-101 borders.
// Input:  d_in[0] = float32 [32,3,512,512]  (96 planes of 512x512)
// Output: d_out   = float32 [32,3,512,512]
//
// The 17x17 kernel is fully determined at compile time:
//   disk(radius=8) normalized by its 197 ones, then 3x3 Gaussian blur
//   (sigma=0.5, reflect-101). We reconstruct it in a constexpr device
//   function so that, after full unrolling, every weight becomes an
//   FFMA immediate (rt_SMSP=1 on Blackwell -> full 128 MAC/cyc/SM) and
//   all zero-weight taps (289 -> 257) are dead-code-eliminated.

__device__ __host__ __forceinline__ constexpr float wval(int i, int j) {
    // i, j in [0,16]; returns blurred-disk weight.
    // Gaussian(sigma=0.5, ksize=3) normalized: exp(-2)=0.13533528...,
    // g = {e2, 1, e2} / (1 + 2*e2)
    const float g0 = 0.10650698f;
    const float g1 = 0.78698604f;
    const float g[3] = {g0, g1, g0};
    float s = 0.0f;
    for (int a = 0; a < 3; ++a) {
        for (int b = 0; b < 3; ++b) {
            int r = i + a - 1;
            int c = j + b - 1;
            // reflect-101 on the 17x17 grid
            r = (r < 0) ? -r : ((r > 16) ? 32 - r : r);
            c = (c < 0) ? -c : ((c > 16) ? 32 - c : c);
            const int dy = r - 8;
            const int dx = c - 8;
            if (dy * dy + dx * dx <= 64) {  // inside disk (radius 8)
                s += g[a] * g[b];
            }
        }
    }
    return s / 197.0f;  // disk has exactly 197 ones
}

// Tile geometry: 64 wide x 32 tall output tile, 8-pixel halo all around.
// Block = 256 threads = 64 (x) x 4 (y-groups); each thread computes an
// 8-row vertical strip of outputs at one x column, so every shared-memory
// load feeds up to 8 FMAs.
#define TILE_W 64
#define TILE_H 32
#define HALO   8
#define SMW    (TILE_W + 2 * HALO)   // 80
#define SMH    (TILE_H + 2 * HALO)   // 48

__global__ void __launch_bounds__(256, 1)
defocus_blur_kernel(const float* __restrict__ in, float* __restrict__ out) {
    __shared__ float S[SMH][SMW];

    const int plane = blockIdx.z;                 // 0..95
    const int X0 = blockIdx.x * TILE_W;
    const int Y0 = blockIdx.y * TILE_H;

    const float* __restrict__ ip = in  + (size_t)plane * 512 * 512;
    float* __restrict__       op = out + (size_t)plane * 512 * 512;

    // ---- cooperative tile load with reflect-101 border handling ----
    float* Sf = &S[0][0];
    #pragma unroll
    for (int idx = threadIdx.x; idx < SMH * SMW; idx += 256) {
        const int ly = idx / SMW;
        const int lx = idx - ly * SMW;
        int gy = Y0 - HALO + ly;
        gy = (gy < 0) ? -gy : ((gy > 511) ? 1022 - gy : gy);
        int gx = X0 - HALO + lx;
        gx = (gx < 0) ? -gx : ((gx > 511) ? 1022 - gx : gx);
        Sf[idx] = __ldg(&ip[gy * 512 + gx]);
    }
    __syncthreads();

    const int tx = threadIdx.x & 63;     // x within tile
    const int ty = threadIdx.x >> 6;     // which 8-row group

    float acc[8];
    #pragma unroll
    for (int k = 0; k < 8; ++k) acc[k] = 0.0f;

    const int rbase = ty * 8;  // S-row of r=0 for this thread group

    // r: input row offset relative to (first output row - 8); r in [0,24)
    // output k uses input row r when dy = r - k is in [0,16].
    #pragma unroll
    for (int r = 0; r < 24; ++r) {
        #pragma unroll
        for (int dx = 0; dx < 17; ++dx) {
            const float s = S[rbase + r][tx + dx];
            #pragma unroll
            for (int k = 0; k < 8; ++k) {
                const int dy = r - k;
                if (dy >= 0 && dy <= 16) {
                    const float w = wval(dy, dx);   // compile-time constant
                    if (w != 0.0f) {                // folds: 289 -> 257 taps
                        acc[k] = fmaf(s, w, acc[k]);
                    }
                }
            }
        }
    }

    // ---- store 8 output rows, coalesced 64-wide ----
    const int yo = Y0 + ty * 8;
    #pragma unroll
    for (int k = 0; k < 8; ++k) {
        op[(yo + k) * 512 + X0 + tx] = acc[k];
    }
}

extern "C" void kernel_launch(void* const* d_in, const int* in_sizes, int n_in,
                              void* d_out, int out_size) {
    const float* in = (const float*)d_in[0];
    float* out = (float*)d_out;
    // 32*3 = 96 planes of 512x512; 8 x-tiles, 16 y-tiles per plane.
    dim3 grid(512 / TILE_W, 512 / TILE_H, 96);
    defocus_blur_kernel<<<grid, 256>>>(in, out);
}

// round 2
// speedup vs baseline: 51.3756x; 51.3756x over previous
#include <cuda_runtime.h>
#include <cuda_bf16.h>
#include <utility>

// DefocusBlur: depthwise 17x17 cross-correlation, reflect-101 borders.
// Input:  d_in[0] = float32 [32,3,512,512]  (96 planes of 512x512)
// Output: d_out   = float32 [32,3,512,512]
//
// The 17x17 kernel (disk radius 8, normalized by its 197 ones, then 3x3
// Gaussian sigma=0.5 with reflect-101) is built ONCE at compile time into
// a constexpr table. All tap loops are expanded via template integer
// parameters (fold expressions), so every weight is a syntactic constant
// expression -> FFMA immediate operand (rt_SMSP=1 on Blackwell), zero-weight
// taps are dead-code-eliminated, and the hot loop has no integer ALU.

struct WTab { float w[17][17]; };

__host__ __device__ constexpr WTab make_wtab() {
    WTab t{};
    // Gaussian(sigma=0.5, ksize=3): exp(-2)=0.13533528; normalized.
    const float g0 = 0.10650698f;
    const float g1 = 0.78698604f;
    const float g[3] = {g0, g1, g0};
    for (int i = 0; i < 17; ++i) {
        for (int j = 0; j < 17; ++j) {
            float s = 0.0f;
            for (int a = 0; a < 3; ++a) {
                for (int b = 0; b < 3; ++b) {
                    int r = i + a - 1;
                    int c = j + b - 1;
                    r = (r < 0) ? -r : ((r > 16) ? 32 - r : r);   // reflect-101
                    c = (c < 0) ? -c : ((c > 16) ? 32 - c : c);
                    const int dy = r - 8;
                    const int dx = c - 8;
                    if (dy * dy + dx * dx <= 64) s += g[a] * g[b];
                }
            }
            t.w[i][j] = s / 197.0f;   // disk has exactly 197 ones
        }
    }
    return t;
}

constexpr WTab WT = make_wtab();

#define TILE_W 64
#define TILE_H 32
#define HALO   8
#define SMW    (TILE_W + 2 * HALO)   // 80
#define SMH    (TILE_H + 2 * HALO)   // 48

// ---- one tap: compile-time (R=input-row offset, DX, K=output index) ----
template <int R, int DX, int K>
__device__ __forceinline__ void tap(float s, float* acc) {
    constexpr int dy = R - K;
    if constexpr (dy >= 0 && dy <= 16) {
        constexpr float w = WT.w[dy][DX];      // constant expression -> IMM
        if constexpr (w != 0.0f) {             // DCE: 289 -> 257 taps
            acc[K] = fmaf(s, w, acc[K]);
        }
    }
}

template <int R, int DX, int... Ks>
__device__ __forceinline__ void taps_k(float s, float* acc,
                                       std::integer_sequence<int, Ks...>) {
    (tap<R, DX, Ks>(s, acc), ...);
}

template <int R, int... DXs>
__device__ __forceinline__ void row_taps(const float* __restrict__ Scol,
                                         float* acc,
                                         std::integer_sequence<int, DXs...>) {
    // Scol points at S[rbase + R][tx]; DX offsets become LDS immediates.
    (taps_k<R, DXs>(Scol[DXs], acc, std::make_integer_sequence<int, 8>{}), ...);
}

template <int... Rs>
__device__ __forceinline__ void all_rows(const float* __restrict__ Sbase,
                                         float* acc,
                                         std::integer_sequence<int, Rs...>) {
    // Sbase points at S[rbase][tx]; each row is +SMW floats.
    (row_taps<Rs>(Sbase + Rs * SMW, acc,
                  std::make_integer_sequence<int, 17>{}), ...);
}

__global__ void __launch_bounds__(256)
defocus_blur_kernel(const float* __restrict__ in, float* __restrict__ out) {
    __shared__ float S[SMH][SMW];

    const int plane = blockIdx.z;                 // 0..95
    const int X0 = blockIdx.x * TILE_W;
    const int Y0 = blockIdx.y * TILE_H;

    const float* __restrict__ ip = in  + (size_t)plane * 512 * 512;
    float* __restrict__       op = out + (size_t)plane * 512 * 512;

    // ---- cooperative tile load with reflect-101 border handling ----
    float* Sf = &S[0][0];
    #pragma unroll
    for (int idx = threadIdx.x; idx < SMH * SMW; idx += 256) {
        const int ly = idx / SMW;
        const int lx = idx - ly * SMW;
        int gy = Y0 - HALO + ly;
        gy = (gy < 0) ? -gy : ((gy > 511) ? 1022 - gy : gy);
        int gx = X0 - HALO + lx;
        gx = (gx < 0) ? -gx : ((gx > 511) ? 1022 - gx : gx);
        Sf[idx] = __ldg(&ip[gy * 512 + gx]);
    }
    __syncthreads();

    const int tx = threadIdx.x & 63;     // x within tile
    const int ty = threadIdx.x >> 6;     // which 8-row output group

    float acc[8];
    #pragma unroll
    for (int k = 0; k < 8; ++k) acc[k] = 0.0f;

    // Each shared value S[rbase+R][tx+DX] feeds up to 8 output rows.
    all_rows(&S[ty * 8][tx], acc, std::make_integer_sequence<int, 24>{});

    // ---- store 8 output rows, coalesced 64-wide ----
    const int yo = Y0 + ty * 8;
    #pragma unroll
    for (int k = 0; k < 8; ++k) {
        op[(yo + k) * 512 + X0 + tx] = acc[k];
    }
}

extern "C" void kernel_launch(void* const* d_in, const int* in_sizes, int n_in,
                              void* d_out, int out_size) {
    const float* in = (const float*)d_in[0];
    float* out = (float*)d_out;
    dim3 grid(512 / TILE_W, 512 / TILE_H, 96);   // 8 x 16 x 96 = 12288 blocks
    defocus_blur_kernel<<<grid, 256>>>(in, out);
}

// round 3
// speedup vs baseline: 101.2205x; 1.9702x over previous
#include <cuda_runtime.h>
#include <cuda_bf16.h>
#include <utility>

// DefocusBlur: depthwise 17x17 cross-correlation, reflect-101 borders.
// Input:  d_in[0] = float32 [32,3,512,512]; Output same shape.
//
// Strategy (issue-bound kernel -> minimize issued instructions/output):
//  * compile-time weight table -> FFMA immediate form (rt_SMSP=1)
//  * horizontal mirror symmetry: pair sums p[j]=v[8-j]+v[8+j], halving
//    FFMAs per row-dot
//  * vertical mirror symmetry: row-dot d=min(dy,16-dy) shared between the
//    two outputs k=r-dy and k=r-16+dy within a 16-output vertical strip
// Table is symmetrized at construction so the sharing is bit-exact.

struct WTab { float w[17][17]; };

__host__ __device__ constexpr WTab make_wtab() {
    WTab t{};
    const float g0 = 0.10650698f;
    const float g1 = 0.78698604f;
    const float g[3] = {g0, g1, g0};
    for (int i = 0; i < 17; ++i) {
        for (int j = 0; j < 17; ++j) {
            float s = 0.0f;
            for (int a = 0; a < 3; ++a) {
                for (int b = 0; b < 3; ++b) {
                    int r = i + a - 1;
                    int c = j + b - 1;
                    r = (r < 0) ? -r : ((r > 16) ? 32 - r : r);   // reflect-101
                    c = (c < 0) ? -c : ((c > 16) ? 32 - c : c);
                    const int dy = r - 8;
                    const int dx = c - 8;
                    if (dy * dy + dx * dx <= 64) s += g[a] * g[b];
                }
            }
            t.w[i][j] = s / 197.0f;
        }
    }
    // Symmetrize exactly: copy from the canonical quadrant (<=1 ulp change).
    WTab u{};
    for (int i = 0; i < 17; ++i) {
        for (int j = 0; j < 17; ++j) {
            const int ci = (i < 16 - i) ? i : 16 - i;
            const int cj = (j < 16 - j) ? j : 16 - j;
            u.w[i][j] = t.w[ci][cj];
        }
    }
    return u;
}

constexpr WTab WT = make_wtab();

__host__ __device__ constexpr int dmin(int dy) { return (dy < 16 - dy) ? dy : 16 - dy; }

#define KPT 16                      // outputs per thread (vertical strip)
__host__ __device__ constexpr bool needed_rd(int R, int D) {
    for (int k = 0; k < KPT; ++k) {
        const int dy = R - k;
        if (dy >= 0 && dy <= 16 && dmin(dy) == D) return true;
    }
    return false;
}

#define TILE_W 64
#define TILE_H 64
#define HALO   8
#define SMW    (TILE_W + 2 * HALO)   // 80
#define SMH    (TILE_H + 2 * HALO)   // 80

// ---- one symmetric tap pair: acc += w[D][8+J] * (v[8-J]+v[8+J]) ----
template <int D, int J>
__device__ __forceinline__ void pairtap(float& s, const float* p) {
    constexpr float w = WT.w[D][8 + J];     // == WT.w[D][8-J] by construction
    if constexpr (w != 0.0f) s = fmaf(p[J], w, s);
}

template <int D, int... Js>
__device__ __forceinline__ void pairtaps(float& s, const float* p,
                                         std::integer_sequence<int, Js...>) {
    (pairtap<D, Js + 1>(s, p), ...);
}

// ---- row dot for weight-row D (only if some output of this strip needs it)
template <int R, int D>
__device__ __forceinline__ void calc_dot(float* dot, const float* p) {
    if constexpr (needed_rd(R, D)) {
        float s;
        constexpr float wc = WT.w[D][8];
        if constexpr (wc != 0.0f) s = wc * p[0]; else s = 0.0f;
        pairtaps<D>(s, p, std::make_integer_sequence<int, 8>{});
        dot[D] = s;
    }
}

template <int R, int... Ds>
__device__ __forceinline__ void calc_dots(float* dot, const float* p,
                                          std::integer_sequence<int, Ds...>) {
    (calc_dot<R, Ds>(dot, p), ...);
}

// ---- distribute the shared dots into the strip's accumulators ----
template <int R, int K>
__device__ __forceinline__ void comb1(float* acc, const float* dot) {
    constexpr int dy = R - K;
    if constexpr (dy >= 0 && dy <= 16) acc[K] += dot[dmin(dy)];
}

template <int R, int... Ks>
__device__ __forceinline__ void combine(float* acc, const float* dot,
                                        std::integer_sequence<int, Ks...>) {
    (comb1<R, Ks>(acc, dot), ...);
}

template <int R>
__device__ __forceinline__ void do_row(const float* __restrict__ Srow, float* acc) {
    float v[17];
    #pragma unroll
    for (int j = 0; j < 17; ++j) v[j] = Srow[j];    // LDS with imm offsets
    float p[9];
    p[0] = v[8];
    #pragma unroll
    for (int j = 1; j <= 8; ++j) p[j] = v[8 - j] + v[8 + j];
    float dot[9];
    calc_dots<R>(dot, p, std::make_integer_sequence<int, 9>{});
    combine<R>(acc, dot, std::make_integer_sequence<int, KPT>{});
}

template <int... Rs>
__device__ __forceinline__ void all_rows(const float* __restrict__ Sbase,
                                         float* acc,
                                         std::integer_sequence<int, Rs...>) {
    (do_row<Rs>(Sbase + Rs * SMW, acc), ...);
}

__global__ void __launch_bounds__(256)
defocus_blur_kernel(const float* __restrict__ in, float* __restrict__ out) {
    __shared__ float S[SMH][SMW];

    const int plane = blockIdx.z;                 // 0..95
    const int X0 = blockIdx.x * TILE_W;
    const int Y0 = blockIdx.y * TILE_H;

    const float* __restrict__ ip = in  + (size_t)plane * 512 * 512;
    float* __restrict__       op = out + (size_t)plane * 512 * 512;

    // ---- cooperative tile load, reflect-101 borders (6400 elems, 25/thread)
    float* Sf = &S[0][0];
    #pragma unroll
    for (int idx = threadIdx.x; idx < SMH * SMW; idx += 256) {
        const int ly = idx / SMW;
        const int lx = idx - ly * SMW;
        int gy = Y0 - HALO + ly;
        gy = (gy < 0) ? -gy : ((gy > 511) ? 1022 - gy : gy);
        int gx = X0 - HALO + lx;
        gx = (gx < 0) ? -gx : ((gx > 511) ? 1022 - gx : gx);
        Sf[idx] = __ldg(&ip[gy * 512 + gx]);
    }
    __syncthreads();

    const int tx = threadIdx.x & 63;     // x within tile
    const int ty = threadIdx.x >> 6;     // which 16-row output strip

    float acc[KPT];
    #pragma unroll
    for (int k = 0; k < KPT; ++k) acc[k] = 0.0f;

    // Strip covers input rows [ty*16, ty*16+31] of the padded tile.
    all_rows(&S[ty * KPT][tx], acc, std::make_integer_sequence<int, KPT + 16>{});

    // ---- store 16 output rows, coalesced 64-wide ----
    const int yo = Y0 + ty * KPT;
    #pragma unroll
    for (int k = 0; k < KPT; ++k) {
        op[(yo + k) * 512 + X0 + tx] = acc[k];
    }
}

extern "C" void kernel_launch(void* const* d_in, const int* in_sizes, int n_in,
                              void* d_out, int out_size) {
    const float* in = (const float*)d_in[0];
    float* out = (float*)d_out;
    dim3 grid(512 / TILE_W, 512 / TILE_H, 96);   // 8 x 8 x 96 = 6144 blocks
    defocus_blur_kernel<<<grid, 256>>>(in, out);
}